// round 1
// baseline (speedup 1.0000x reference)
#include <cuda_runtime.h>
#include <math.h>

#define NB 8
#define SL 4096
#define HD 128
#define CCH 128
#define NCH (SL / CCH)   // 32

// Scratch (no allocations allowed): ~54 MB total
__device__ float g_cos[SL * HD];
__device__ float g_sin[SL * HD];
__device__ float g_qr [NB * SL * HD];           // RoPE'd Q, natural [b][s][d]
__device__ float g_krT[NB * NCH * HD * CCH];    // RoPE'd K, chunk-transposed [b][ch][d][t]
__device__ float g_h  [NB * NCH * HD * HD];     // per-chunk K^T V -> exclusive prefix states

// ---------------------------------------------------------------------------
// Kernel 0: RoPE cos/sin table (double internally for accuracy)
// ---------------------------------------------------------------------------
__global__ void k_tab() {
    int s = blockIdx.x;
    int j = threadIdx.x;
    int j2 = j & 63;
    double inv = exp(-(double)j2 * (log(10000.0) / 64.0));
    double a = (double)s * inv;
    double sv, cv;
    sincos(a, &sv, &cv);
    g_cos[s * HD + j] = (float)cv;
    g_sin[s * HD + j] = (float)sv;
}

// ---------------------------------------------------------------------------
// Kernel 1: apply RoPE. Q -> g_qr (natural), K -> g_krT (transposed per chunk)
// One block per (b, chunk). Dynamic smem: 128*129 floats (66048 B).
// ---------------------------------------------------------------------------
__global__ void __launch_bounds__(256) k_rope(const float* __restrict__ Q,
                                              const float* __restrict__ K) {
    extern __shared__ float buf[];   // [128][129] padded
    int b  = blockIdx.x >> 5;
    int ch = blockIdx.x & 31;
    int tid = threadIdx.x;
    int base = (b * SL + ch * CCH) * HD;

    // ---- Q path: load raw tile, rope, write natural ----
    #pragma unroll 4
    for (int k = 0; k < 64; ++k) {
        int idx = tid + k * 256;
        int t = idx >> 7, d = idx & 127;
        buf[t * 129 + d] = Q[base + idx];
    }
    __syncthreads();
    #pragma unroll 4
    for (int k = 0; k < 64; ++k) {
        int idx = tid + k * 256;
        int t = idx >> 7, d = idx & 127;
        int s = ch * CCH + t;
        float x  = buf[t * 129 + d];
        float xo = buf[t * 129 + (d ^ 64)];
        float rot = (d < 64) ? -xo : xo;
        g_qr[base + idx] = x * g_cos[s * HD + d] + rot * g_sin[s * HD + d];
    }
    __syncthreads();

    // ---- K path: load raw tile, rope into regs, smem-transpose, write ----
    #pragma unroll 4
    for (int k = 0; k < 64; ++k) {
        int idx = tid + k * 256;
        int t = idx >> 7, d = idx & 127;
        buf[t * 129 + d] = K[base + idx];
    }
    __syncthreads();
    float kreg[64];
    #pragma unroll 4
    for (int k = 0; k < 64; ++k) {
        int idx = tid + k * 256;
        int t = idx >> 7, d = idx & 127;
        int s = ch * CCH + t;
        float x  = buf[t * 129 + d];
        float xo = buf[t * 129 + (d ^ 64)];
        float rot = (d < 64) ? -xo : xo;
        kreg[k] = x * g_cos[s * HD + d] + rot * g_sin[s * HD + d];
    }
    __syncthreads();
    #pragma unroll 4
    for (int k = 0; k < 64; ++k) {
        int idx = tid + k * 256;
        int t = idx >> 7, d = idx & 127;
        buf[d * 129 + t] = kreg[k];   // transposed, conflict-free (stride 129)
    }
    __syncthreads();
    int kb = (b * NCH + ch) * HD * CCH;
    #pragma unroll 4
    for (int k = 0; k < 64; ++k) {
        int idx = tid + k * 256;
        int dd = idx >> 7, tt = idx & 127;
        g_krT[kb + idx] = buf[dd * 129 + tt];   // coalesced write of [d][t]
    }
}

// ---------------------------------------------------------------------------
// 128x128x128 fp32 smem GEMM micro-kernel. 256 threads as 16x16, 8x8 tiles.
// A: row-major [128][128], accessed A[r][k] -> broadcast scalar LDS (no conflicts)
// B: row-major [128][128], accessed B[k][c..c+7] -> float4 LDS (standard pattern)
// ---------------------------------------------------------------------------
__device__ __forceinline__ void mm128(const float* __restrict__ sA,
                                      const float* __restrict__ sB,
                                      float acc[8][8], int r0, int c0) {
    #pragma unroll 4
    for (int k = 0; k < 128; ++k) {
        float a[8];
        #pragma unroll
        for (int i = 0; i < 8; ++i) a[i] = sA[(r0 + i) * 128 + k];
        float4 b0 = *(const float4*)(sB + k * 128 + c0);
        float4 b1 = *(const float4*)(sB + k * 128 + c0 + 4);
        float bb[8] = {b0.x, b0.y, b0.z, b0.w, b1.x, b1.y, b1.z, b1.w};
        #pragma unroll
        for (int i = 0; i < 8; ++i)
            #pragma unroll
            for (int j = 0; j < 8; ++j)
                acc[i][j] = fmaf(a[i], bb[j], acc[i][j]);
    }
}

// ---------------------------------------------------------------------------
// Kernel 2: per-chunk H = Kr^T V  (H[d][e] = sum_t KrT[d][t] * V[t][e])
// One block per (b, chunk). Dynamic smem 128 KB.
// ---------------------------------------------------------------------------
__global__ void __launch_bounds__(256) k_h(const float* __restrict__ V) {
    extern __shared__ float sm[];
    float* sA = sm;            // KrT [d][t]
    float* sB = sm + 16384;    // V   [t][e]
    int b  = blockIdx.x >> 5;
    int ch = blockIdx.x & 31;
    int tid = threadIdx.x;
    int kb = (b * NCH + ch) * 16384;
    int vb = (b * SL + ch * CCH) * HD;
    #pragma unroll 4
    for (int k = 0; k < 64; ++k) {
        int idx = tid + k * 256;
        sA[idx] = g_krT[kb + idx];
        sB[idx] = V[vb + idx];
    }
    __syncthreads();
    int ty = tid >> 4, tx = tid & 15;
    int r0 = ty * 8, c0 = tx * 8;
    float acc[8][8] = {};
    mm128(sA, sB, acc, r0, c0);
    #pragma unroll
    for (int i = 0; i < 8; ++i) {
        float4* p = (float4*)(g_h + kb + (r0 + i) * 128 + c0);
        p[0] = make_float4(acc[i][0], acc[i][1], acc[i][2], acc[i][3]);
        p[1] = make_float4(acc[i][4], acc[i][5], acc[i][6], acc[i][7]);
    }
}

// ---------------------------------------------------------------------------
// Kernel 3: in-place exclusive prefix scan of H over chunks (per b, per row d)
// ---------------------------------------------------------------------------
__global__ void k_scan() {
    int b = blockIdx.x;
    int d = blockIdx.y;
    int e = threadIdx.x;
    float run = 0.f;
    for (int i = 0; i < NCH; ++i) {
        int idx = ((b * NCH + i) * HD + d) * HD + e;
        float v = g_h[idx];
        g_h[idx] = run;
        run += v;
    }
}

// ---------------------------------------------------------------------------
// Kernel 4: out = tril(Qr Kr^T) V + Qr S_excl  per (b, chunk).
// Dynamic smem 192 KB: sQ (Qr), sX (KrT -> E), sY (S -> V).
// ---------------------------------------------------------------------------
__global__ void __launch_bounds__(256) k_out(const float* __restrict__ V,
                                             float* __restrict__ out) {
    extern __shared__ float sm[];
    float* sQ = sm;            // Qr [r][d]
    float* sX = sm + 16384;    // KrT [d][t], later E [r][t]
    float* sY = sm + 32768;    // S [d][c],  later V [t][c]
    int b  = blockIdx.x >> 5;
    int ch = blockIdx.x & 31;
    int tid = threadIdx.x;
    int qb = (b * SL + ch * CCH) * HD;
    int kb = (b * NCH + ch) * 16384;

    #pragma unroll 4
    for (int k = 0; k < 64; ++k) {
        int idx = tid + k * 256;
        sQ[idx] = g_qr[qb + idx];
        sX[idx] = g_krT[kb + idx];
        sY[idx] = g_h[kb + idx];
    }
    __syncthreads();

    int ty = tid >> 4, tx = tid & 15;
    int r0 = ty * 8, c0 = tx * 8;

    // Phase 1: E = Qr @ KrT   (E[r][t] = sum_d Qr[r][d] * KrT[d][t])
    float eacc[8][8] = {};
    mm128(sQ, sX, eacc, r0, c0);
    __syncthreads();   // all reads of sX (KrT) complete

    // Mask (causal within chunk: keep t <= r) and store E into sX
    #pragma unroll
    for (int i = 0; i < 8; ++i) {
        #pragma unroll
        for (int j = 0; j < 8; ++j)
            if (c0 + j > r0 + i) eacc[i][j] = 0.f;
        float4* p = (float4*)(sX + (r0 + i) * 128 + c0);
        p[0] = make_float4(eacc[i][0], eacc[i][1], eacc[i][2], eacc[i][3]);
        p[1] = make_float4(eacc[i][4], eacc[i][5], eacc[i][6], eacc[i][7]);
    }

    // Phase 2: acc = Qr @ S_excl  (reads sQ, sY; independent of sX writes)
    float acc[8][8] = {};
    mm128(sQ, sY, acc, r0, c0);
    __syncthreads();   // E stores visible; sY reads complete

    // Phase 3: load V over S, acc += E @ V
    #pragma unroll 4
    for (int k = 0; k < 64; ++k) {
        int idx = tid + k * 256;
        sY[idx] = V[qb + idx];
    }
    __syncthreads();
    mm128(sX, sY, acc, r0, c0);

    // Write output
    #pragma unroll
    for (int i = 0; i < 8; ++i) {
        float4* p = (float4*)(out + qb + (r0 + i) * 128 + c0);
        p[0] = make_float4(acc[i][0], acc[i][1], acc[i][2], acc[i][3]);
        p[1] = make_float4(acc[i][4], acc[i][5], acc[i][6], acc[i][7]);
    }
}

// ---------------------------------------------------------------------------
extern "C" void kernel_launch(void* const* d_in, const int* in_sizes, int n_in,
                              void* d_out, int out_size) {
    (void)in_sizes; (void)n_in; (void)out_size;
    const float* Q = (const float*)d_in[0];
    const float* K = (const float*)d_in[1];
    const float* V = (const float*)d_in[2];
    float* out = (float*)d_out;

    cudaFuncSetAttribute(k_rope, cudaFuncAttributeMaxDynamicSharedMemorySize, 66048);
    cudaFuncSetAttribute(k_h,    cudaFuncAttributeMaxDynamicSharedMemorySize, 131072);
    cudaFuncSetAttribute(k_out,  cudaFuncAttributeMaxDynamicSharedMemorySize, 196608);

    k_tab <<<SL, HD>>>();
    k_rope<<<NB * NCH, 256, 66048>>>(Q, K);
    k_h   <<<NB * NCH, 256, 131072>>>(V);
    k_scan<<<dim3(NB, HD), HD>>>();
    k_out <<<NB * NCH, 256, 196608>>>(V, out);
}

// round 2
// speedup vs baseline: 1.0275x; 1.0275x over previous
#include <cuda_runtime.h>
#include <math.h>

#define NB 8
#define SL 4096
#define HD 128
#define CCH 128
#define NCH (SL / CCH)   // 32

typedef unsigned long long ull;

// Scratch (no allocations allowed): ~54 MB total
__device__ float g_cos[SL * HD];
__device__ float g_sin[SL * HD];
__device__ float g_qr [NB * SL * HD];           // RoPE'd Q, natural [b][s][d]
__device__ float g_krT[NB * NCH * HD * CCH];    // RoPE'd K, chunk-transposed [b][ch][d][t]
__device__ float g_h  [NB * NCH * HD * HD];     // per-chunk K^T V -> exclusive prefix states

// ---------------------------------------------------------------------------
// packed f32x2 helpers (sm_100a; ptxas never emits FFMA2 from C++)
// ---------------------------------------------------------------------------
__device__ __forceinline__ ull pk2(float x) {
    ull r;
    asm("mov.b64 %0, {%1, %1};" : "=l"(r) : "f"(x));
    return r;
}
__device__ __forceinline__ void ffma2(ull& d, ull a, ull b) {
    asm("fma.rn.f32x2 %0, %1, %2, %0;" : "+l"(d) : "l"(a), "l"(b));
}

// ---------------------------------------------------------------------------
// Kernel 0: RoPE cos/sin table (double internally for accuracy)
// ---------------------------------------------------------------------------
__global__ void k_tab() {
    int s = blockIdx.x;
    int j = threadIdx.x;
    int j2 = j & 63;
    double inv = exp(-(double)j2 * (log(10000.0) / 64.0));
    double a = (double)s * inv;
    double sv, cv;
    sincos(a, &sv, &cv);
    g_cos[s * HD + j] = (float)cv;
    g_sin[s * HD + j] = (float)sv;
}

// ---------------------------------------------------------------------------
// Kernel 1: apply RoPE. Q -> g_qr (natural), K -> g_krT (transposed per chunk)
// ---------------------------------------------------------------------------
__global__ void __launch_bounds__(256) k_rope(const float* __restrict__ Q,
                                              const float* __restrict__ K) {
    extern __shared__ float buf[];   // [128][129] padded
    int b  = blockIdx.x >> 5;
    int ch = blockIdx.x & 31;
    int tid = threadIdx.x;
    int base = (b * SL + ch * CCH) * HD;

    // ---- Q path ----
    #pragma unroll 4
    for (int k = 0; k < 64; ++k) {
        int idx = tid + k * 256;
        int t = idx >> 7, d = idx & 127;
        buf[t * 129 + d] = Q[base + idx];
    }
    __syncthreads();
    #pragma unroll 4
    for (int k = 0; k < 64; ++k) {
        int idx = tid + k * 256;
        int t = idx >> 7, d = idx & 127;
        int s = ch * CCH + t;
        float x  = buf[t * 129 + d];
        float xo = buf[t * 129 + (d ^ 64)];
        float rot = (d < 64) ? -xo : xo;
        g_qr[base + idx] = x * g_cos[s * HD + d] + rot * g_sin[s * HD + d];
    }
    __syncthreads();

    // ---- K path: rope into regs, smem-transpose, write [d][t] ----
    #pragma unroll 4
    for (int k = 0; k < 64; ++k) {
        int idx = tid + k * 256;
        int t = idx >> 7, d = idx & 127;
        buf[t * 129 + d] = K[base + idx];
    }
    __syncthreads();
    float kreg[64];
    #pragma unroll 4
    for (int k = 0; k < 64; ++k) {
        int idx = tid + k * 256;
        int t = idx >> 7, d = idx & 127;
        int s = ch * CCH + t;
        float x  = buf[t * 129 + d];
        float xo = buf[t * 129 + (d ^ 64)];
        float rot = (d < 64) ? -xo : xo;
        kreg[k] = x * g_cos[s * HD + d] + rot * g_sin[s * HD + d];
    }
    __syncthreads();
    #pragma unroll 4
    for (int k = 0; k < 64; ++k) {
        int idx = tid + k * 256;
        int t = idx >> 7, d = idx & 127;
        buf[d * 129 + t] = kreg[k];
    }
    __syncthreads();
    int kb = (b * NCH + ch) * HD * CCH;
    #pragma unroll 4
    for (int k = 0; k < 64; ++k) {
        int idx = tid + k * 256;
        int dd = idx >> 7, tt = idx & 127;
        g_krT[kb + idx] = buf[dd * 129 + tt];
    }
}

// ---------------------------------------------------------------------------
// 128x128x128 fp32 smem GEMM micro-kernel with packed fma.rn.f32x2.
// 256 threads as 16x16, each an 8x8 output tile held as ull acc[8][4].
// A: row-major, A[r][k] broadcast scalar LDS, packed {a,a} via mov.b64.
// B: row-major, B[k][c..c+7] via two 16B LDS (pairs are FFMA2 lanes).
// ---------------------------------------------------------------------------
__device__ __forceinline__ void mm128_f2(const float* __restrict__ sA,
                                         const float* __restrict__ sB,
                                         ull acc[8][4], int r0, int c0) {
    #pragma unroll 4
    for (int k = 0; k < 128; ++k) {
        ull ap[8];
        #pragma unroll
        for (int i = 0; i < 8; ++i) ap[i] = pk2(sA[(r0 + i) * 128 + k]);
        ulonglong2 b01 = *(const ulonglong2*)(sB + k * 128 + c0);
        ulonglong2 b23 = *(const ulonglong2*)(sB + k * 128 + c0 + 4);
        ull bb[4] = {b01.x, b01.y, b23.x, b23.y};
        #pragma unroll
        for (int i = 0; i < 8; ++i)
            #pragma unroll
            for (int j = 0; j < 4; ++j)
                ffma2(acc[i][j], ap[i], bb[j]);
    }
}

// ---------------------------------------------------------------------------
// Kernel 2: per-chunk H = Kr^T V  (H[d][e] = sum_t KrT[d][t] * V[t][e])
// ---------------------------------------------------------------------------
__global__ void __launch_bounds__(256) k_h(const float* __restrict__ V) {
    extern __shared__ float sm[];
    float* sA = sm;            // KrT [d][t]
    float* sB = sm + 16384;    // V   [t][e]
    int b  = blockIdx.x >> 5;
    int ch = blockIdx.x & 31;
    int tid = threadIdx.x;
    int kb = (b * NCH + ch) * 16384;
    int vb = (b * SL + ch * CCH) * HD;
    #pragma unroll 4
    for (int k = 0; k < 64; ++k) {
        int idx = tid + k * 256;
        sA[idx] = g_krT[kb + idx];
        sB[idx] = V[vb + idx];
    }
    __syncthreads();
    int ty = tid >> 4, tx = tid & 15;
    int r0 = ty * 8, c0 = tx * 8;
    ull acc[8][4] = {};
    mm128_f2(sA, sB, acc, r0, c0);
    #pragma unroll
    for (int i = 0; i < 8; ++i) {
        const float* f = (const float*)acc[i];
        float4* p = (float4*)(g_h + kb + (r0 + i) * 128 + c0);
        p[0] = make_float4(f[0], f[1], f[2], f[3]);
        p[1] = make_float4(f[4], f[5], f[6], f[7]);
    }
}

// ---------------------------------------------------------------------------
// Kernel 3: in-place exclusive prefix scan of H over chunks (float4 wide)
// ---------------------------------------------------------------------------
__global__ void k_scan() {
    int b = blockIdx.x;
    int d = blockIdx.y;
    int e4 = threadIdx.x;   // 0..31, each owns 4 columns
    float4 run = make_float4(0.f, 0.f, 0.f, 0.f);
    #pragma unroll 4
    for (int i = 0; i < NCH; ++i) {
        float4* p = (float4*)(g_h + ((b * NCH + i) * HD + d) * HD) + e4;
        float4 v = *p;
        *p = run;
        run.x += v.x; run.y += v.y; run.z += v.z; run.w += v.w;
    }
}

// ---------------------------------------------------------------------------
// Kernel 4: out = tril(Qr Kr^T) V + Qr S_excl  per (b, chunk).
// Dynamic smem 192 KB: sQ (Qr), sX (KrT -> E), sY (S -> V).
// ---------------------------------------------------------------------------
__global__ void __launch_bounds__(256) k_out(const float* __restrict__ V,
                                             float* __restrict__ out) {
    extern __shared__ float sm[];
    float* sQ = sm;            // Qr [r][d]
    float* sX = sm + 16384;    // KrT [d][t], later E [r][t]
    float* sY = sm + 32768;    // S [d][c],  later V [t][c]
    int b  = blockIdx.x >> 5;
    int ch = blockIdx.x & 31;
    int tid = threadIdx.x;
    int qb = (b * SL + ch * CCH) * HD;
    int kb = (b * NCH + ch) * 16384;

    #pragma unroll 4
    for (int k = 0; k < 64; ++k) {
        int idx = tid + k * 256;
        sQ[idx] = g_qr[qb + idx];
        sX[idx] = g_krT[kb + idx];
        sY[idx] = g_h[kb + idx];
    }
    __syncthreads();

    int ty = tid >> 4, tx = tid & 15;
    int r0 = ty * 8, c0 = tx * 8;

    // Phase 1: E = Qr @ KrT
    ull eacc[8][4] = {};
    mm128_f2(sQ, sX, eacc, r0, c0);
    __syncthreads();   // all reads of sX (KrT) complete

    // Mask (causal within chunk: keep t <= r) and store E into sX
    #pragma unroll
    for (int i = 0; i < 8; ++i) {
        float* f = (float*)eacc[i];
        #pragma unroll
        for (int j = 0; j < 8; ++j)
            if (c0 + j > r0 + i) f[j] = 0.f;
        float4* p = (float4*)(sX + (r0 + i) * 128 + c0);
        p[0] = make_float4(f[0], f[1], f[2], f[3]);
        p[1] = make_float4(f[4], f[5], f[6], f[7]);
    }

    // Phase 2: acc = Qr @ S_excl
    ull acc[8][4] = {};
    mm128_f2(sQ, sY, acc, r0, c0);
    __syncthreads();   // E stores visible; sY reads complete

    // Phase 3: load V over S, acc += E @ V
    #pragma unroll 4
    for (int k = 0; k < 64; ++k) {
        int idx = tid + k * 256;
        sY[idx] = V[qb + idx];
    }
    __syncthreads();
    mm128_f2(sX, sY, acc, r0, c0);

    // Write output
    #pragma unroll
    for (int i = 0; i < 8; ++i) {
        const float* f = (const float*)acc[i];
        float4* p = (float4*)(out + qb + (r0 + i) * 128 + c0);
        p[0] = make_float4(f[0], f[1], f[2], f[3]);
        p[1] = make_float4(f[4], f[5], f[6], f[7]);
    }
}

// ---------------------------------------------------------------------------
extern "C" void kernel_launch(void* const* d_in, const int* in_sizes, int n_in,
                              void* d_out, int out_size) {
    (void)in_sizes; (void)n_in; (void)out_size;
    const float* Q = (const float*)d_in[0];
    const float* K = (const float*)d_in[1];
    const float* V = (const float*)d_in[2];
    float* out = (float*)d_out;

    cudaFuncSetAttribute(k_rope, cudaFuncAttributeMaxDynamicSharedMemorySize, 66048);
    cudaFuncSetAttribute(k_h,    cudaFuncAttributeMaxDynamicSharedMemorySize, 131072);
    cudaFuncSetAttribute(k_out,  cudaFuncAttributeMaxDynamicSharedMemorySize, 196608);

    k_tab <<<SL, HD>>>();
    k_rope<<<NB * NCH, 256, 66048>>>(Q, K);
    k_h   <<<NB * NCH, 256, 131072>>>(V);
    k_scan<<<dim3(NB, HD), 32>>>();
    k_out <<<NB * NCH, 256, 196608>>>(V, out);
}

// round 4
// speedup vs baseline: 1.9343x; 1.8825x over previous
#include <cuda_runtime.h>
#include <cuda_bf16.h>
#include <math.h>

#define NB 8
#define SL 4096
#define HD 128
#define CCH 128
#define NCH (SL / CCH)   // 32
#define NT  (NB * NCH)   // 256 tiles

#define TPAD 136                     // padded bf16 row stride in smem tiles
#define TILE_BYTES (128 * TPAD * 2)  // 34816

typedef unsigned int u32;

// ---------------------------------------------------------------------------
// Scratch (no allocations allowed): ~80 MB
// ---------------------------------------------------------------------------
__device__ float g_cos[SL * HD];
__device__ float g_sin[SL * HD];
__device__ float g_h  [NT * HD * HD];           // per-chunk H[d][e] fp32
__device__ __nv_bfloat16 g_q_hi [NT * 16384];   // Qr  [t][d]
__device__ __nv_bfloat16 g_q_lo [NT * 16384];
__device__ __nv_bfloat16 g_kT_hi[NT * 16384];   // Kr^T [d][t]
__device__ __nv_bfloat16 g_kT_lo[NT * 16384];
__device__ __nv_bfloat16 g_v_hi [NT * 16384];   // V   [t][e]
__device__ __nv_bfloat16 g_v_lo [NT * 16384];
__device__ __nv_bfloat16 g_s_hi [NT * 16384];   // S excl prefix [d][e]
__device__ __nv_bfloat16 g_s_lo [NT * 16384];

// ---------------------------------------------------------------------------
// Warp MMA primitives (baseline PTX: sm_80-class, valid on plain sm_100)
// ---------------------------------------------------------------------------
__device__ __forceinline__ u32 smem_u32(const void* p) {
    u32 a;
    asm("{ .reg .u64 t; cvta.to.shared.u64 t, %1; cvt.u32.u64 %0, t; }"
        : "=r"(a) : "l"(p));
    return a;
}
__device__ __forceinline__ void ldsm4(u32& r0, u32& r1, u32& r2, u32& r3, u32 a) {
    asm volatile("ldmatrix.sync.aligned.m8n8.x4.shared.b16 {%0,%1,%2,%3}, [%4];"
                 : "=r"(r0), "=r"(r1), "=r"(r2), "=r"(r3) : "r"(a));
}
__device__ __forceinline__ void ldsm4t(u32& r0, u32& r1, u32& r2, u32& r3, u32 a) {
    asm volatile("ldmatrix.sync.aligned.m8n8.x4.trans.shared.b16 {%0,%1,%2,%3}, [%4];"
                 : "=r"(r0), "=r"(r1), "=r"(r2), "=r"(r3) : "r"(a));
}
__device__ __forceinline__ void mma_bf16(float* c, u32 a0, u32 a1, u32 a2, u32 a3,
                                         u32 b0, u32 b1) {
    asm volatile(
        "mma.sync.aligned.m16n8k16.row.col.f32.bf16.bf16.f32 "
        "{%0,%1,%2,%3},{%4,%5,%6,%7},{%8,%9},{%0,%1,%2,%3};"
        : "+f"(c[0]), "+f"(c[1]), "+f"(c[2]), "+f"(c[3])
        : "r"(a0), "r"(a1), "r"(a2), "r"(a3), "r"(b0), "r"(b1));
}
__device__ __forceinline__ u32 packbf(__nv_bfloat16 lo, __nv_bfloat16 hi) {
    return (u32)__bfloat16_as_ushort(hi) << 16 | (u32)__bfloat16_as_ushort(lo);
}
__device__ __forceinline__ void split_store(__nv_bfloat16* hi, __nv_bfloat16* lo,
                                            int off, float v) {
    __nv_bfloat16 h = __float2bfloat16(v);
    hi[off] = h;
    lo[off] = __float2bfloat16(v - __bfloat162float(h));
}

// gmem [128][128] bf16 tile -> smem padded [128][TPAD]
__device__ __forceinline__ void copy_tile(char* dst, const __nv_bfloat16* src, int tid) {
    const uint4* s = (const uint4*)src;
    #pragma unroll
    for (int i = 0; i < 8; ++i) {
        int j = tid + i * 256;
        int row = j >> 4, col = j & 15;
        *(uint4*)(dst + row * (TPAD * 2) + col * 16) = s[j];
    }
}

// ---------------------------------------------------------------------------
// 3-term split GEMM, warp tile 16x128, K=128.
// A row-major [M][K] (hi/lo smem), B row-major [K][N] (hi/lo smem).
// acc[16][4] = 16 n8-fragments of m16n8 fp32.
// ---------------------------------------------------------------------------
__device__ __forceinline__ void gemm3(u32 ah, u32 al, u32 bh, u32 bl,
                                      float acc[16][4], int m0, int lane) {
    int l15 = lane & 15, lhi = (lane >> 4) << 3;
    #pragma unroll 1
    for (int kk = 0; kk < 8; ++kk) {
        u32 aoff = (u32)(((m0 + l15) * TPAD + kk * 16 + lhi) * 2);
        u32 A0, A1, A2, A3, L0, L1, L2, L3;
        ldsm4(A0, A1, A2, A3, ah + aoff);
        ldsm4(L0, L1, L2, L3, al + aoff);
        #pragma unroll
        for (int nt = 0; nt < 8; ++nt) {
            u32 boff = (u32)(((kk * 16 + l15) * TPAD + nt * 16 + lhi) * 2);
            u32 B0, B1, B2, B3, C0, C1, C2, C3;
            ldsm4t(B0, B1, B2, B3, bh + boff);
            ldsm4t(C0, C1, C2, C3, bl + boff);
            mma_bf16(acc[2 * nt],     A0, A1, A2, A3, B0, B1);
            mma_bf16(acc[2 * nt + 1], A0, A1, A2, A3, B2, B3);
            mma_bf16(acc[2 * nt],     A0, A1, A2, A3, C0, C1);
            mma_bf16(acc[2 * nt + 1], A0, A1, A2, A3, C2, C3);
            mma_bf16(acc[2 * nt],     L0, L1, L2, L3, B0, B1);
            mma_bf16(acc[2 * nt + 1], L0, L1, L2, L3, B2, B3);
        }
    }
}

// Same, but A comes from in-register E fragments (eh/el), K=128.
__device__ __forceinline__ void gemm_e(const u32 eh[16][2], const u32 el[16][2],
                                       u32 bh, u32 bl, float acc[16][4], int lane) {
    int l15 = lane & 15, lhi = (lane >> 4) << 3;
    #pragma unroll
    for (int kk = 0; kk < 8; ++kk) {
        u32 A0 = eh[2 * kk][0], A1 = eh[2 * kk][1];
        u32 A2 = eh[2 * kk + 1][0], A3 = eh[2 * kk + 1][1];
        u32 L0 = el[2 * kk][0], L1 = el[2 * kk][1];
        u32 L2 = el[2 * kk + 1][0], L3 = el[2 * kk + 1][1];
        #pragma unroll
        for (int nt = 0; nt < 8; ++nt) {
            u32 boff = (u32)(((kk * 16 + l15) * TPAD + nt * 16 + lhi) * 2);
            u32 B0, B1, B2, B3, C0, C1, C2, C3;
            ldsm4t(B0, B1, B2, B3, bh + boff);
            ldsm4t(C0, C1, C2, C3, bl + boff);
            mma_bf16(acc[2 * nt],     A0, A1, A2, A3, B0, B1);
            mma_bf16(acc[2 * nt + 1], A0, A1, A2, A3, B2, B3);
            mma_bf16(acc[2 * nt],     A0, A1, A2, A3, C0, C1);
            mma_bf16(acc[2 * nt + 1], A0, A1, A2, A3, C2, C3);
            mma_bf16(acc[2 * nt],     L0, L1, L2, L3, B0, B1);
            mma_bf16(acc[2 * nt + 1], L0, L1, L2, L3, B2, B3);
        }
    }
}

// ---------------------------------------------------------------------------
// Kernel 0: RoPE cos/sin table (double internally)
// ---------------------------------------------------------------------------
__global__ void k_tab() {
    int s = blockIdx.x;
    int j = threadIdx.x;
    int j2 = j & 63;
    double inv = exp(-(double)j2 * (log(10000.0) / 64.0));
    double a = (double)s * inv;
    double sv, cv;
    sincos(a, &sv, &cv);
    g_cos[s * HD + j] = (float)cv;
    g_sin[s * HD + j] = (float)sv;
}

// ---------------------------------------------------------------------------
// Kernel 1: RoPE + split-bf16. Q -> g_q [t][d]; K -> g_kT [d][t]; V -> g_v.
// smem: one padded fp32 buf [128][129] for the K transpose only.
// ---------------------------------------------------------------------------
__global__ void __launch_bounds__(256) k_rope(const float* __restrict__ Q,
                                              const float* __restrict__ K,
                                              const float* __restrict__ V) {
    extern __shared__ float buf[];   // [128][129]
    int b  = blockIdx.x >> 5;
    int ch = blockIdx.x & 31;
    int tid = threadIdx.x;
    int base  = (b * SL + ch * CCH) * HD;
    int tbase = blockIdx.x * 16384;

    #pragma unroll 4
    for (int i = 0; i < 64; ++i) {
        int idx = tid + i * 256;
        int t = idx >> 7, d = idx & 127;
        int s = ch * CCH + t;
        float cs = g_cos[s * HD + d], sn = g_sin[s * HD + d];
        // Q
        float x  = Q[base + idx];
        float xo = Q[base + (idx ^ 64)];
        float rot = (d < 64) ? -xo : xo;
        split_store(g_q_hi, g_q_lo, tbase + idx, x * cs + rot * sn);
        // V (no rope)
        split_store(g_v_hi, g_v_lo, tbase + idx, V[base + idx]);
        // K roped -> smem for transpose
        float kx  = K[base + idx];
        float kxo = K[base + (idx ^ 64)];
        float krot = (d < 64) ? -kxo : kxo;
        buf[t * 129 + d] = kx * cs + krot * sn;
    }
    __syncthreads();
    #pragma unroll 4
    for (int i = 0; i < 64; ++i) {
        int idx = tid + i * 256;
        int d = idx >> 7, t = idx & 127;
        split_store(g_kT_hi, g_kT_lo, tbase + idx, buf[t * 129 + d]);
    }
}

// ---------------------------------------------------------------------------
// Kernel 2: per-chunk H[d][e] = sum_t Kr^T[d][t] * V[t][e]  (HMMA, 3-term)
// smem: KTh, KTl, Vh, Vl padded tiles (139264 B)
// ---------------------------------------------------------------------------
__global__ void __launch_bounds__(256) k_h() {
    extern __shared__ char sm[];
    u32 sb = smem_u32(sm);
    int tile = blockIdx.x;
    int tid = threadIdx.x, lane = tid & 31, wid = tid >> 5;

    copy_tile(sm,                  g_kT_hi + tile * 16384, tid);
    copy_tile(sm + TILE_BYTES,     g_kT_lo + tile * 16384, tid);
    copy_tile(sm + 2 * TILE_BYTES, g_v_hi  + tile * 16384, tid);
    copy_tile(sm + 3 * TILE_BYTES, g_v_lo  + tile * 16384, tid);
    __syncthreads();

    float acc[16][4] = {};
    int m0 = wid * 16;
    gemm3(sb, sb + TILE_BYTES, sb + 2 * TILE_BYTES, sb + 3 * TILE_BYTES,
          acc, m0, lane);

    int r = m0 + (lane >> 2), cb = (lane & 3) * 2;
    float* dst = g_h + tile * 16384;
    #pragma unroll
    for (int j = 0; j < 16; ++j) {
        int c = 8 * j + cb;
        *(float2*)(dst + r * 128 + c)       = make_float2(acc[j][0], acc[j][1]);
        *(float2*)(dst + (r + 8) * 128 + c) = make_float2(acc[j][2], acc[j][3]);
    }
}

// ---------------------------------------------------------------------------
// Kernel 3: exclusive prefix scan of H over chunks -> split-bf16 S tiles.
// One block per (b, d); 128 threads (one per e).
// ---------------------------------------------------------------------------
__global__ void __launch_bounds__(128) k_scan() {
    int b = blockIdx.x, d = blockIdx.y, e = threadIdx.x;
    float vals[NCH];
    #pragma unroll
    for (int i = 0; i < NCH; ++i)
        vals[i] = g_h[(b * NCH + i) * 16384 + d * 128 + e];
    int o = d * 128 + e;
    float run = 0.f;
    #pragma unroll
    for (int i = 0; i < NCH; ++i) {
        int tb = (b * NCH + i) * 16384;
        split_store(g_s_hi, g_s_lo, tb + o, run);
        run += vals[i];
    }
}

// ---------------------------------------------------------------------------
// Kernel 4: out = tril(Qr Kr^T) V + Qr S  per (b, chunk).
// smem slots (139264 B): slot0/1 = Q (later V), slot2/3 = KrT (later S).
// ---------------------------------------------------------------------------
__global__ void __launch_bounds__(256) k_out(float* __restrict__ out) {
    extern __shared__ char sm[];
    u32 sb = smem_u32(sm);
    int tile = blockIdx.x;
    int tid = threadIdx.x, lane = tid & 31, wid = tid >> 5;
    int qb = tile * 16384;   // == (b*SL + ch*CCH)*HD
    int m0 = wid * 16;

    // stage 1: Q + KrT
    copy_tile(sm,                  g_q_hi  + qb, tid);
    copy_tile(sm + TILE_BYTES,     g_q_lo  + qb, tid);
    copy_tile(sm + 2 * TILE_BYTES, g_kT_hi + qb, tid);
    copy_tile(sm + 3 * TILE_BYTES, g_kT_lo + qb, tid);
    __syncthreads();

    // phase 1: E = Qr @ Kr^T
    float eacc[16][4] = {};
    gemm3(sb, sb + TILE_BYTES, sb + 2 * TILE_BYTES, sb + 3 * TILE_BYTES,
          eacc, m0, lane);

    // mask (causal within chunk) + split to bf16 A-fragments in registers
    u32 eh[16][2], el[16][2];
    {
        int r = m0 + (lane >> 2), cb = (lane & 3) * 2;
        #pragma unroll
        for (int j = 0; j < 16; ++j) {
            int c = 8 * j + cb;
            float v0 = (c     <= r)     ? eacc[j][0] : 0.f;
            float v1 = (c + 1 <= r)     ? eacc[j][1] : 0.f;
            float v2 = (c     <= r + 8) ? eacc[j][2] : 0.f;
            float v3 = (c + 1 <= r + 8) ? eacc[j][3] : 0.f;
            __nv_bfloat16 h0 = __float2bfloat16(v0), h1 = __float2bfloat16(v1);
            __nv_bfloat16 h2 = __float2bfloat16(v2), h3 = __float2bfloat16(v3);
            eh[j][0] = packbf(h0, h1);
            eh[j][1] = packbf(h2, h3);
            el[j][0] = packbf(__float2bfloat16(v0 - __bfloat162float(h0)),
                              __float2bfloat16(v1 - __bfloat162float(h1)));
            el[j][1] = packbf(__float2bfloat16(v2 - __bfloat162float(h2)),
                              __float2bfloat16(v3 - __bfloat162float(h3)));
        }
    }
    __syncthreads();   // all warps done reading KrT

    // stage 2: S over KrT
    copy_tile(sm + 2 * TILE_BYTES, g_s_hi + qb, tid);
    copy_tile(sm + 3 * TILE_BYTES, g_s_lo + qb, tid);
    __syncthreads();

    // phase 2: O = Qr @ S
    float oacc[16][4] = {};
    gemm3(sb, sb + TILE_BYTES, sb + 2 * TILE_BYTES, sb + 3 * TILE_BYTES,
          oacc, m0, lane);
    __syncthreads();   // all warps done reading Q

    // stage 3: V over Q
    copy_tile(sm,              g_v_hi + qb, tid);
    copy_tile(sm + TILE_BYTES, g_v_lo + qb, tid);
    __syncthreads();

    // phase 3: O += E @ V  (A from registers)
    gemm_e(eh, el, sb, sb + TILE_BYTES, oacc, lane);

    // epilogue
    int r = m0 + (lane >> 2), cb = (lane & 3) * 2;
    float* dst = out + qb;
    #pragma unroll
    for (int j = 0; j < 16; ++j) {
        int c = 8 * j + cb;
        *(float2*)(dst + r * 128 + c)       = make_float2(oacc[j][0], oacc[j][1]);
        *(float2*)(dst + (r + 8) * 128 + c) = make_float2(oacc[j][2], oacc[j][3]);
    }
}

// ---------------------------------------------------------------------------
extern "C" void kernel_launch(void* const* d_in, const int* in_sizes, int n_in,
                              void* d_out, int out_size) {
    (void)in_sizes; (void)n_in; (void)out_size;
    const float* Q = (const float*)d_in[0];
    const float* K = (const float*)d_in[1];
    const float* V = (const float*)d_in[2];
    float* out = (float*)d_out;

    cudaFuncSetAttribute(k_rope, cudaFuncAttributeMaxDynamicSharedMemorySize, 66048);
    cudaFuncSetAttribute(k_h,    cudaFuncAttributeMaxDynamicSharedMemorySize, 4 * TILE_BYTES);
    cudaFuncSetAttribute(k_out,  cudaFuncAttributeMaxDynamicSharedMemorySize, 4 * TILE_BYTES);

    k_tab <<<SL, HD>>>();
    k_rope<<<NT, 256, 66048>>>(Q, K, V);
    k_h   <<<NT, 256, 4 * TILE_BYTES>>>();
    k_scan<<<dim3(NB, HD), 128>>>();
    k_out <<<NT, 256, 4 * TILE_BYTES>>>(out);
}